// round 3
// baseline (speedup 1.0000x reference)
#include <cuda_runtime.h>
#include <math.h>

#define BB 32
#define S2 32
#define HH 1024
#define DHEAD 64
#define NLAY 4
#define THIST 8
#define TACT 8
#define HINN 512
#define MR (BB*S2)
#define WSOSPLIT 16

__device__ float d_pe[S2*HH];
__device__ float d_tokens[MR*HH];
__device__ float d_h[MR*HH];
__device__ float d_qb[MR*HH];
__device__ float d_kb[MR*HH];
__device__ float d_vb[MR*HH];
__device__ float d_ctx[MR*HH];
__device__ float d_p0[MR*HH];
__device__ float d_p1[MR*HH];
__device__ float d_prev[NLAY][MR*HH];
__device__ float d_aemb[BB*TACT*HH];
__device__ float d_snew[BB*HINN];
__device__ float d_wsop[WSOSPLIT*BB*HINN];

__global__ void pe_kernel(){
  int pos = blockIdx.x;
  for (int d = threadIdx.x; d < HH; d += blockDim.x){
    double e = (double)(2*(d>>1)) / (double)HH;
    double ang = (double)pos / pow(10000.0, e);
    d_pe[pos*HH+d] = (float)((d&1) ? cos(ang) : sin(ang));
  }
}

// hsEmb in d_qb, haEmb in d_kb, sEmb in d_vb at call time
__global__ void init_tokens(){
  int s = blockIdx.x, b = blockIdx.y;
  const float* src = nullptr;
  if (s < 2*THIST)       src = ((s&1) ? d_kb : d_qb) + (size_t)(b*THIST + (s>>1))*HH;
  else if (s == 2*THIST) src = d_vb + (size_t)b*HH;
  float* dst = d_tokens + (size_t)(b*S2+s)*HH;
  for (int d = threadIdx.x; d < HH; d += blockDim.x) dst[d] = src ? src[d] : 0.f;
}

__global__ void build_h(int step){
  int s = blockIdx.x, b = blockIdx.y;
  int pos_a = 2*THIST + 1 + 2*step;
  int L = pos_a + 1;
  float* tok = d_tokens + (size_t)(b*S2+s)*HH;
  float* hp  = d_h + (size_t)(b*S2+s)*HH;
  const float* ae = d_aemb + (size_t)(b*TACT + step)*HH;
  for (int d = threadIdx.x; d < HH; d += blockDim.x){
    float t;
    if (s == pos_a){ t = ae[d]; tok[d] = t; } else t = tok[d];
    hp[d] = t + ((s < L) ? d_pe[s*HH+d] : 0.f);
  }
}

struct GemmZ { const float* A; const float* W; float* C; int kBeg, kEnd, M, lda; };
struct GemmArgs { GemmZ z[4]; int ldc; int act; };

__global__ void __launch_bounds__(256,2) gemm_kernel(GemmArgs ga){
  GemmZ gz = ga.z[blockIdx.z];
  int mBase = blockIdx.y*128;
  if (mBase >= gz.M) return;
  int nBase = blockIdx.x*128;
  int tid = threadIdx.x, tx = tid&15, ty = tid>>4;
  __shared__ float As[2][16][128];
  __shared__ float Bs[2][16][128];
  int arow[2], ak4[2], brow[2], bc4[2]; bool aok[2];
  #pragma unroll
  for (int i=0;i<2;i++){
    int f = tid + i*256;
    arow[i]=f>>2; ak4[i]=f&3; aok[i]=(mBase+arow[i])<gz.M;
    brow[i]=f>>5; bc4[i]=f&31;
  }
  int nt = (gz.kEnd - gz.kBeg)>>4;
  float4 av[2], bv[2];
  {
    int k0 = gz.kBeg;
    #pragma unroll
    for (int i=0;i<2;i++){
      av[i] = aok[i] ? *(const float4*)(gz.A + (size_t)(mBase+arow[i])*gz.lda + k0 + ak4[i]*4)
                     : make_float4(0.f,0.f,0.f,0.f);
      bv[i] = *(const float4*)(gz.W + (size_t)(k0+brow[i])*HH + nBase + bc4[i]*4);
    }
    #pragma unroll
    for (int i=0;i<2;i++){
      As[0][ak4[i]*4+0][arow[i]]=av[i].x; As[0][ak4[i]*4+1][arow[i]]=av[i].y;
      As[0][ak4[i]*4+2][arow[i]]=av[i].z; As[0][ak4[i]*4+3][arow[i]]=av[i].w;
      *(float4*)&Bs[0][brow[i]][bc4[i]*4] = bv[i];
    }
  }
  __syncthreads();
  float acc[8][8];
  #pragma unroll
  for (int r=0;r<8;r++)
    #pragma unroll
    for (int c=0;c<8;c++) acc[r][c]=0.f;
  int buf=0;
  for (int t=0;t<nt;t++){
    if (t+1<nt){
      int k0 = gz.kBeg + (t+1)*16;
      #pragma unroll
      for (int i=0;i<2;i++){
        av[i] = aok[i] ? *(const float4*)(gz.A + (size_t)(mBase+arow[i])*gz.lda + k0 + ak4[i]*4)
                       : make_float4(0.f,0.f,0.f,0.f);
        bv[i] = *(const float4*)(gz.W + (size_t)(k0+brow[i])*HH + nBase + bc4[i]*4);
      }
    }
    #pragma unroll
    for (int kk=0;kk<16;kk++){
      float4 a0=*(const float4*)&As[buf][kk][ty*8];
      float4 a1=*(const float4*)&As[buf][kk][ty*8+4];
      float4 b0=*(const float4*)&Bs[buf][kk][tx*8];
      float4 b1=*(const float4*)&Bs[buf][kk][tx*8+4];
      float a[8]={a0.x,a0.y,a0.z,a0.w,a1.x,a1.y,a1.z,a1.w};
      float bb[8]={b0.x,b0.y,b0.z,b0.w,b1.x,b1.y,b1.z,b1.w};
      #pragma unroll
      for (int r=0;r<8;r++)
        #pragma unroll
        for (int c=0;c<8;c++) acc[r][c]=fmaf(a[r],bb[c],acc[r][c]);
    }
    if (t+1<nt){
      buf^=1;
      #pragma unroll
      for (int i=0;i<2;i++){
        As[buf][ak4[i]*4+0][arow[i]]=av[i].x; As[buf][ak4[i]*4+1][arow[i]]=av[i].y;
        As[buf][ak4[i]*4+2][arow[i]]=av[i].z; As[buf][ak4[i]*4+3][arow[i]]=av[i].w;
        *(float4*)&Bs[buf][brow[i]][bc4[i]*4]=bv[i];
      }
      __syncthreads();
    }
  }
  #pragma unroll
  for (int r=0;r<8;r++){
    int grow = mBase + ty*8 + r;
    if (grow < gz.M){
      float* cp = gz.C + (size_t)grow*ga.ldc + nBase + tx*8;
      #pragma unroll
      for (int c=0;c<8;c++){
        float v = acc[r][c];
        if (ga.act) v = v>0.f ? v : 0.f;
        cp[c] = v;
      }
    }
  }
}

__global__ void attn_kernel(int L){
  __shared__ float Qs[S2][DHEAD];
  __shared__ float Ks[S2][DHEAD+1];
  __shared__ float Vs[S2][DHEAD];
  __shared__ float Ps[S2][S2+1];
  int bh = blockIdx.x, b = bh>>4, hd = bh&15, tid = threadIdx.x;
  const float* qb = d_qb + (size_t)(b*S2)*HH + hd*DHEAD;
  const float* kb = d_kb + (size_t)(b*S2)*HH + hd*DHEAD;
  const float* vb = d_vb + (size_t)(b*S2)*HH + hd*DHEAD;
  for (int i = tid; i < S2*DHEAD; i += blockDim.x){
    int s=i>>6, d=i&63;
    Qs[s][d]=qb[(size_t)s*HH+d]; Ks[s][d]=kb[(size_t)s*HH+d]; Vs[s][d]=vb[(size_t)s*HH+d];
  }
  __syncthreads();
  for (int i = tid; i < S2*S2; i += blockDim.x){
    int q=i>>5, k=i&31;
    float sc=0.f;
    #pragma unroll
    for (int d=0;d<DHEAD;d++) sc += Qs[q][d]*Ks[k][d];
    sc *= 0.125f;
    if (!(q<L && k<L)) sc = -1e20f;
    Ps[q][k]=sc;
  }
  __syncthreads();
  if (tid < S2){
    int q = tid;
    if (q >= L){ for (int k=0;k<S2;k++) Ps[q][k]=0.f; }
    else {
      float mx=-3.4e38f;
      for (int k=0;k<S2;k++) mx = fmaxf(mx, Ps[q][k]);
      float sum=0.f;
      for (int k=0;k<S2;k++){ float e=expf(Ps[q][k]-mx); Ps[q][k]=e; sum+=e; }
      float inv=1.f/sum;
      for (int k=0;k<S2;k++) Ps[q][k] = (k<L) ? Ps[q][k]*inv : 0.f;
    }
  }
  __syncthreads();
  for (int i = tid; i < S2*DHEAD; i += blockDim.x){
    int q=i>>6, d=i&63;
    float o=0.f;
    #pragma unroll
    for (int k=0;k<S2;k++) o += Ps[q][k]*Vs[k][d];
    d_ctx[(size_t)(b*S2+q)*HH + hd*DHEAD + d] = o;
  }
}

__device__ __forceinline__ float block_sum(float v){
  __shared__ float red[32];
  int lane=threadIdx.x&31, wid=threadIdx.x>>5;
  #pragma unroll
  for (int o=16;o>0;o>>=1) v += __shfl_down_sync(0xffffffffu, v, o);
  if (lane==0) red[wid]=v;
  __syncthreads();
  float r = (threadIdx.x < (blockDim.x>>5)) ? red[threadIdx.x] : 0.f;
  if (wid==0){
    #pragma unroll
    for (int o=16;o>0;o>>=1) r += __shfl_down_sync(0xffffffffu, r, o);
    if (lane==0) red[0]=r;
  }
  __syncthreads();
  float out = red[0];
  __syncthreads();
  return out;
}

__global__ void ln_kernel(const float* __restrict__ x, const float* __restrict__ p0,
                          const float* __restrict__ p1, const float* __restrict__ g,
                          const float* __restrict__ bia, float* out, float* out2){
  int row = blockIdx.x, tid = threadIdx.x;
  float v[4]; float s=0.f;
  #pragma unroll
  for (int i=0;i<4;i++){
    size_t off = (size_t)row*HH + tid + i*256;
    float t = x[off]+p0[off]+p1[off];
    v[i]=t; s+=t;
  }
  float mean = block_sum(s)*(1.f/HH);
  float s2=0.f;
  #pragma unroll
  for (int i=0;i<4;i++){ float dd=v[i]-mean; s2+=dd*dd; }
  float inv = 1.f/sqrtf(block_sum(s2)*(1.f/HH) + 1e-5f);
  #pragma unroll
  for (int i=0;i<4;i++){
    int d = tid + i*256;
    size_t off = (size_t)row*HH + d;
    float y = (v[i]-mean)*inv*g[d] + bia[d];
    out[off]=y;
    if (out2) out2[off]=y;
  }
}

__global__ void wr_kernel(const float* __restrict__ Wr, float* out, int step){
  int b = blockIdx.x;
  float s=0.f;
  const float* hf = d_h + (size_t)b*S2*HH;
  for (int x = threadIdx.x; x < S2*HH; x += blockDim.x) s += hf[x]*Wr[x];
  s = block_sum(s);
  if (threadIdx.x==0) out[b*TACT+step] = 1.f/(1.f+expf(-s));
}

__global__ void wso_part(const float* __restrict__ Wso){
  int nb = blockIdx.x, sp = blockIdx.y, tid = threadIdx.x;
  int tx = tid&63, tg = tid>>6;
  __shared__ float Asm[32][33];
  __shared__ float Wsm[32][64];
  float acc[8];
  #pragma unroll
  for (int r=0;r<8;r++) acc[r]=0.f;
  const int kLen = (S2*HH)/WSOSPLIT, k0 = sp*kLen;
  for (int kc=0; kc<kLen; kc+=32){
    for (int i=tid; i<32*32; i+=256){
      int bq=i>>5, kk=i&31;
      Asm[bq][kk] = d_h[(size_t)bq*S2*HH + k0+kc+kk];
    }
    for (int i=tid; i<32*64; i+=256){
      int kk=i>>6, cc=i&63;
      Wsm[kk][cc] = Wso[(size_t)(k0+kc+kk)*HINN + nb*64 + cc];
    }
    __syncthreads();
    #pragma unroll
    for (int kk=0;kk<32;kk++){
      float w = Wsm[kk][tx];
      #pragma unroll
      for (int r=0;r<8;r++) acc[r] = fmaf(Asm[tg*8+r][kk], w, acc[r]);
    }
    __syncthreads();
  }
  #pragma unroll
  for (int r=0;r<8;r++)
    d_wsop[(size_t)sp*BB*HINN + (size_t)(tg*8+r)*HINN + nb*64 + tx] = acc[r];
}

__global__ void wso_reduce(float* out, int step){
  int b = blockIdx.x, n = threadIdx.x;
  float s=0.f;
  #pragma unroll
  for (int sp=0;sp<WSOSPLIT;sp++) s += d_wsop[(size_t)sp*BB*HINN + (size_t)b*HINN + n];
  s = fmaxf(s, 0.f);
  d_snew[b*HINN+n] = s;
  out[BB*TACT + (size_t)(b*TACT+step)*HINN + n] = s;
}

static void* sym(const void* s){ void* p = nullptr; cudaGetSymbolAddress(&p, s); return p; }

extern "C" void kernel_launch(void* const* d_in, const int* in_sizes, int n_in,
                              void* d_out, int out_size){
  (void)in_sizes; (void)n_in; (void)out_size;
  const float* hist_s=(const float*)d_in[0];
  const float* hist_a=(const float*)d_in[1];
  const float* s_in  =(const float*)d_in[2];
  const float* a_list=(const float*)d_in[3];
  const float* Ws =(const float*)d_in[4];
  const float* Wa =(const float*)d_in[5];
  const float* Wq =(const float*)d_in[6];
  const float* Wk =(const float*)d_in[7];
  const float* Wv =(const float*)d_in[8];
  const float* Wo =(const float*)d_in[9];
  const float* Wfc=(const float*)d_in[10];
  const float* ln1g=(const float*)d_in[11];
  const float* ln1b=(const float*)d_in[12];
  const float* ln2g=(const float*)d_in[13];
  const float* ln2b=(const float*)d_in[14];
  const float* Wr =(const float*)d_in[15];
  const float* Wso=(const float*)d_in[16];
  float* out = (float*)d_out;

  float* ph   =(float*)sym(d_h);
  float* pq   =(float*)sym(d_qb);
  float* pk   =(float*)sym(d_kb);
  float* pv   =(float*)sym(d_vb);
  float* pctx =(float*)sym(d_ctx);
  float* pp0  =(float*)sym(d_p0);
  float* pp1  =(float*)sym(d_p1);
  float* pprev=(float*)sym(d_prev);
  float* pae  =(float*)sym(d_aemb);
  float* psn  =(float*)sym(d_snew);
  float* ptok =(float*)sym(d_tokens);

  pe_kernel<<<S2,256>>>();

  // fused embeddings: hs->d_qb, ha->d_kb, sEmb->d_vb, aemb(all steps)->d_aemb
  {
    GemmArgs ga{};
    ga.ldc=HH; ga.act=1;
    ga.z[0]=GemmZ{hist_s, Ws, pq, 0, HINN, BB*THIST, HINN};
    ga.z[1]=GemmZ{hist_a, Wa, pk, 0, 64,   BB*THIST, 64};
    ga.z[2]=GemmZ{s_in,   Ws, pv, 0, HINN, BB,       HINN};
    ga.z[3]=GemmZ{a_list, Wa, pae,0, 64,   BB*TACT,  64};
    gemm_kernel<<<dim3(8,2,4),256>>>(ga);
  }
  init_tokens<<<dim3(S2,BB),256>>>();

  for (int i=0;i<TACT;i++){
    int L = 2*THIST + 2 + 2*i;
    build_h<<<dim3(S2,BB),256>>>(i);
    for (int j=0;j<NLAY;j++){
      const float* qk = (i==0) ? ph : (pprev + (size_t)j*MR*HH);
      // QKV fused
      {
        GemmArgs ga{};
        ga.ldc=HH; ga.act=0;
        ga.z[0]=GemmZ{qk, Wq+(size_t)j*HH*HH, pq, 0, HH, MR, HH};
        ga.z[1]=GemmZ{qk, Wk+(size_t)j*HH*HH, pk, 0, HH, MR, HH};
        ga.z[2]=GemmZ{ph, Wv+(size_t)j*HH*HH, pv, 0, HH, MR, HH};
        gemm_kernel<<<dim3(8,8,3),256>>>(ga);
      }
      attn_kernel<<<BB*16,256>>>(L);
      // O-projection split-K
      {
        GemmArgs ga{};
        ga.ldc=HH; ga.act=0;
        ga.z[0]=GemmZ{pctx, Wo+(size_t)j*HH*HH, pp0, 0,   HH/2, MR, HH};
        ga.z[1]=GemmZ{pctx, Wo+(size_t)j*HH*HH, pp1, HH/2, HH,  MR, HH};
        gemm_kernel<<<dim3(8,8,2),256>>>(ga);
      }
      ln_kernel<<<MR,256>>>(ph, pp0, pp1, ln1g+(size_t)j*HH, ln1b+(size_t)j*HH, ph, nullptr);
      // FC split-K
      {
        GemmArgs ga{};
        ga.ldc=HH; ga.act=0;
        ga.z[0]=GemmZ{ph, Wfc+(size_t)j*HH*HH, pp0, 0,   HH/2, MR, HH};
        ga.z[1]=GemmZ{ph, Wfc+(size_t)j*HH*HH, pp1, HH/2, HH,  MR, HH};
        gemm_kernel<<<dim3(8,8,2),256>>>(ga);
      }
      ln_kernel<<<MR,256>>>(ph, pp0, pp1, ln2g+(size_t)j*HH, ln2b+(size_t)j*HH, ph,
                            pprev + (size_t)j*MR*HH);
    }
    wr_kernel<<<BB,1024>>>(Wr, out, i);
    wso_part<<<dim3(8,WSOSPLIT),256>>>(Wso);
    wso_reduce<<<BB,HINN>>>(out, i);
    if (i+1 < TACT){
      int pos_s = 2*THIST + 2 + 2*i;
      GemmArgs ga{};
      ga.ldc=S2*HH; ga.act=1;
      ga.z[0]=GemmZ{psn, Ws, ptok + (size_t)pos_s*HH, 0, HINN, BB, HINN};
      gemm_kernel<<<dim3(8,1,1),256>>>(ga);
    }
  }
}